// round 15
// baseline (speedup 1.0000x reference)
#include <cuda_runtime.h>
#include <cstdint>

#define TT 8192
#define DD 2048

typedef unsigned long long ull;

// ---------------- device scratch (no allocations allowed) ----------------
__device__ float g_pre[(size_t)TT * DD];        // 64 MB: pre = x @ W1^T + b1
__device__ float g_hs[(size_t)(TT + 1) * DD];   // 64 MB: h per step; sign bit = not-ready
#define TILES_M 64   // TT/128
#define TILES_N 16   // DD/128
__device__ int g_tile_cnt[TILES_M];             // per-m-tile completion counters

// ---------------- packed f32x2 helpers ----------------
__device__ __forceinline__ ull pk(float lo, float hi) {
    ull r;
    asm("mov.b64 %0, {%1, %2};" : "=l"(r) : "f"(lo), "f"(hi));
    return r;
}
__device__ __forceinline__ void upk(ull v, float& lo, float& hi) {
    asm("mov.b64 {%0, %1}, %2;" : "=f"(lo), "=f"(hi) : "l"(v));
}
__device__ __forceinline__ void fma2(ull& d, ull a, ull b) {
    asm("fma.rn.f32x2 %0, %1, %2, %0;" : "+l"(d) : "l"(a), "l"(b));
}

// ---------------- volatile ld/st (morally strong, guaranteed fresh+live) ----------
__device__ __forceinline__ uint4 ldvol_v4(const float* p) {
    uint4 v;
    asm volatile("ld.volatile.global.v4.u32 {%0,%1,%2,%3}, [%4];"
                 : "=r"(v.x), "=r"(v.y), "=r"(v.z), "=r"(v.w) : "l"(p));
    return v;
}
__device__ __forceinline__ void stvol_f32(float* p, float v) {
    asm volatile("st.volatile.global.f32 [%0], %1;" :: "l"(p), "f"(v));
}
__device__ __forceinline__ int ldvol_s32(const int* p) {
    int v;
    asm volatile("ld.volatile.global.s32 %0, [%1];" : "=r"(v) : "l"(p));
    return v;
}

// wait until pre m-tile is fully produced (checked once per 128 steps)
__device__ __forceinline__ void wait_tile(int m) {
    const int* p = g_tile_cnt + m;
    int v = ldvol_s32(p);
    while (v < TILES_N) {
        __nanosleep(100);
        v = ldvol_s32(p);
    }
    __threadfence();   // acquire: order subsequent pre reads after counter observation
}

// ---------------- poison kernel: not-ready sign bits + counter reset ----------
__global__ void poison_kernel() {
    if (blockIdx.x == 0 && threadIdx.x < TILES_M) g_tile_cnt[threadIdx.x] = 0;
    uint4 p = make_uint4(0xFFFFFFFFu, 0xFFFFFFFFu, 0xFFFFFFFFu, 0xFFFFFFFFu);
    size_t n = (size_t)(TT + 1) * DD / 4;
    uint4* dst = (uint4*)g_hs;
    for (size_t i = (size_t)blockIdx.x * blockDim.x + threadIdx.x; i < n;
         i += (size_t)gridDim.x * blockDim.x)
        dst[i] = p;
}

// ---------------- fused persistent kernel: scan CTAs + gemm CTAs ----------------
#define NCTA 128     // scan CTAs
#define NG   20      // gemm CTAs (remaining SMs; 148 total = all wave-1 resident)
#define NTH  512
#define ROWS 16      // DD / NCTA rows per scan CTA; warp w owns row blk*16+w
#define LDP 132      // padded gemm smem row

// ---- gemm part: 512 threads, persistent over tiles in m-major order ----
__device__ void gemm_part(float* smem, const float* __restrict__ A,
                          const float* __restrict__ B,
                          const float* __restrict__ bias, int g)
{
    float* As = smem;              // [16][LDP]
    float* Bs = smem + 16 * LDP;   // [16][LDP]
    const int tid = threadIdx.x;
    const int tx = tid & 31;       // 32 col-threads (4 cols each)
    const int ty = tid >> 5;       // 16 row-threads (8 rows each)
    const int lr = tid >> 2;       // load row 0..127
    const int lc = (tid & 3) * 4;  // load col group

    for (int idx = g; idx < TILES_M * TILES_N; idx += NG) {
        const int m0 = (idx >> 4) * 128;
        const int n0 = (idx & 15) * 128;

        ull acc[8][2];
#pragma unroll
        for (int r = 0; r < 8; r++) { acc[r][0] = 0ull; acc[r][1] = 0ull; }

        for (int k0 = 0; k0 < DD; k0 += 16) {
            float4 va = *(const float4*)(A + (size_t)(m0 + lr) * DD + k0 + lc);
            As[(lc + 0) * LDP + lr] = va.x; As[(lc + 1) * LDP + lr] = va.y;
            As[(lc + 2) * LDP + lr] = va.z; As[(lc + 3) * LDP + lr] = va.w;
            float4 vb = *(const float4*)(B + (size_t)(n0 + lr) * DD + k0 + lc);
            Bs[(lc + 0) * LDP + lr] = vb.x; Bs[(lc + 1) * LDP + lr] = vb.y;
            Bs[(lc + 2) * LDP + lr] = vb.z; Bs[(lc + 3) * LDP + lr] = vb.w;
            __syncthreads();

#pragma unroll
            for (int k = 0; k < 16; k++) {
                float4 a0 = *(const float4*)&As[k * LDP + ty * 8];
                float4 a1 = *(const float4*)&As[k * LDP + ty * 8 + 4];
                ulonglong2 bq = *(const ulonglong2*)&Bs[k * LDP + tx * 4];
                float ar[8] = {a0.x, a0.y, a0.z, a0.w, a1.x, a1.y, a1.z, a1.w};
#pragma unroll
                for (int r = 0; r < 8; r++) {
                    ull ad = pk(ar[r], ar[r]);
                    fma2(acc[r][0], ad, bq.x);
                    fma2(acc[r][1], ad, bq.y);
                }
            }
            __syncthreads();
        }

        // epilogue: bias + store
        float4 bb = *(const float4*)(bias + n0 + tx * 4);
#pragma unroll
        for (int r = 0; r < 8; r++) {
            float c0, c1, c2, c3;
            upk(acc[r][0], c0, c1);
            upk(acc[r][1], c2, c3);
            float4 o = make_float4(c0 + bb.x, c1 + bb.y, c2 + bb.z, c3 + bb.w);
            *(float4*)(g_pre + (size_t)(m0 + ty * 8 + r) * DD + n0 + tx * 4) = o;
        }

        __threadfence();      // release: pre stores visible before counter bump
        __syncthreads();
        if (tid == 0) atomicAdd(&g_tile_cnt[idx >> 4], 1);
        __syncthreads();
    }
}

// ---- scan step body: k-chunk 8, rows 8 per thread (half-split) ----
// thread tid: half = tid>>8 (rows [half*8, half*8+8)), u = tid&255, k in [8u, 8u+8)
struct StepCtx {
    ull w2[8][4];                 // 8 rows x 4 packed pairs (8 k-values)
    int tid, lane, wid, u, jbase, myrow;
    float myb2;
};

__device__ __forceinline__ void step_body(
    const StepCtx& c, float* s_buf,            // [16][256] partials (16 KB)
    ull h01, ull h23, ull h45, ull h67,
    float pre_cur, float* hstore)
{
#pragma unroll
    for (int j = 0; j < 8; j++) {
        ull acc = 0ull;
        fma2(acc, c.w2[j][0], h01);
        fma2(acc, c.w2[j][1], h23);
        fma2(acc, c.w2[j][2], h45);
        fma2(acc, c.w2[j][3], h67);
        float lo, hi;
        upk(acc, lo, hi);
        s_buf[(c.jbase + j) * 256 + c.u] = lo + hi;
    }
    __syncthreads();

    // warp `wid` reduces row `wid`: 256 partials via 2 x LDS.128 per lane
    const float* rowp = s_buf + c.wid * 256;
    float4 v0 = *(const float4*)(rowp + c.lane * 4);
    float4 v1 = *(const float4*)(rowp + 128 + c.lane * 4);
    float s = ((v0.x + v0.y) + (v0.z + v0.w)) + ((v1.x + v1.y) + (v1.z + v1.w));
    s += __shfl_xor_sync(0xffffffffu, s, 16);
    s += __shfl_xor_sync(0xffffffffu, s, 8);
    s += __shfl_xor_sync(0xffffffffu, s, 4);
    s += __shfl_xor_sync(0xffffffffu, s, 2);
    s += __shfl_xor_sync(0xffffffffu, s, 1);

    if (c.lane == 0) {
        float y = fmaxf(s + pre_cur + c.myb2, 0.f);
        y = __uint_as_float(__float_as_uint(y) & 0x7FFFFFFFu);  // sign bit = ready tag
        stvol_f32(hstore, y);
    }
    // no trailing barrier: double-buffered s_part + per-step BAR + dataflow poll
}

__global__ __launch_bounds__(NTH, 1) void fused_kernel(
    const float* __restrict__ x,
    const float* __restrict__ h0,
    const float* __restrict__ W1,
    const float* __restrict__ b1,
    const float* __restrict__ W2,
    const float* __restrict__ b2)
{
    extern __shared__ float smem[];   // scan: 2*16KB partial buffers; gemm: 17KB

    if (blockIdx.x >= NCTA) {         // ---- gemm CTAs ----
        gemm_part(smem, x, W1, b1, blockIdx.x - NCTA);
        return;
    }

    // ---- scan CTAs ----
    StepCtx c;
    c.tid   = threadIdx.x;
    c.lane  = c.tid & 31;
    c.wid   = c.tid >> 5;
    c.u     = c.tid & 255;
    c.jbase = (c.tid >> 8) * 8;
    const int blk = blockIdx.x;
    const int k0  = c.u * 8;

    // register-resident W2 slab: rows [blk*16+jbase, +8), cols [k0, k0+8)
#pragma unroll
    for (int j = 0; j < 8; j++) {
        const float* wrow = W2 + (size_t)(blk * ROWS + c.jbase + j) * DD + k0;
        float4 wa = *(const float4*)(wrow);
        float4 wb = *(const float4*)(wrow + 4);
        c.w2[j][0] = pk(wa.x, wa.y);
        c.w2[j][1] = pk(wa.z, wa.w);
        c.w2[j][2] = pk(wb.x, wb.y);
        c.w2[j][3] = pk(wb.z, wb.w);
    }
    c.myrow = blk * ROWS + c.wid;
    c.myb2  = b2[c.myrow];

    wait_tile(0);                               // gate pre[0..127]
    float pre_next = __ldg(&g_pre[c.myrow]);

    // ---- step 0 (h0 is input; no poll, may be negative) ----
    {
        float4 ha = *(const float4*)(h0 + k0);
        float4 hb = *(const float4*)(h0 + k0 + 4);
        float pre_cur = pre_next;
        pre_next = __ldg(&g_pre[(size_t)1 * DD + c.myrow]);
        step_body(c, smem, pk(ha.x, ha.y), pk(ha.z, ha.w),
                  pk(hb.x, hb.y), pk(hb.z, hb.w), pre_cur,
                  &g_hs[(size_t)1 * DD + c.myrow]);
    }

    // ---- steps 1..TT-1 ----
    for (int t = 1; t < TT; t++) {
        const float* src = g_hs + (size_t)t * DD + k0;
        uint4 a = ldvol_v4(src);
        uint4 b = ldvol_v4(src + 4);
        while (((a.x | a.y | a.z | a.w | b.x | b.y | b.z | b.w) & 0x80000000u) != 0u) {
            __nanosleep(40);
            a = ldvol_v4(src);
            b = ldvol_v4(src + 4);
        }
        float pre_cur = pre_next;
        if (t + 1 < TT) {
            if (((t + 1) & 127) == 0) wait_tile((t + 1) >> 7);  // gate next m-tile
            pre_next = __ldg(&g_pre[(size_t)(t + 1) * DD + c.myrow]);
        }

        step_body(c, smem + (t & 1) * (ROWS * 256),
                  pk(__uint_as_float(a.x), __uint_as_float(a.y)),
                  pk(__uint_as_float(a.z), __uint_as_float(a.w)),
                  pk(__uint_as_float(b.x), __uint_as_float(b.y)),
                  pk(__uint_as_float(b.z), __uint_as_float(b.w)),
                  pre_cur, &g_hs[(size_t)(t + 1) * DD + c.myrow]);
    }
}

// ---------------- final tiny matvec: out[j] = h . Wf[j] + bf[j] ----------------
__global__ void final_kernel(const float* __restrict__ Wf,
                             const float* __restrict__ bf,
                             float* __restrict__ out)
{
    const int wid = threadIdx.x >> 5;   // 4 warps, one per output row
    const int lane = threadIdx.x & 31;
    const float* h = g_hs + (size_t)TT * DD;
    const float* w = Wf + (size_t)wid * DD;
    float s = 0.f;
#pragma unroll
    for (int i = 0; i < 16; i++) {
        int k = i * 128 + lane * 4;
        float4 hv = *(const float4*)(h + k);
        float4 wv = *(const float4*)(w + k);
        s += hv.x * wv.x + hv.y * wv.y + hv.z * wv.z + hv.w * wv.w;
    }
    for (int off = 16; off; off >>= 1) s += __shfl_xor_sync(0xffffffffu, s, off);
    if (lane == 0) out[wid] = s + bf[wid];
}

// ---------------- dummy kernel: steers ncu's fixed "-s 5" onto fused_kernel ------
__global__ void dummy_kernel() {}

// ---------------- launch ----------------
extern "C" void kernel_launch(void* const* d_in, const int* in_sizes, int n_in,
                              void* d_out, int out_size)
{
    const float* x  = (const float*)d_in[0];
    const float* h0 = (const float*)d_in[1];
    const float* W1 = (const float*)d_in[2];
    const float* b1 = (const float*)d_in[3];
    const float* W2 = (const float*)d_in[4];
    const float* b2 = (const float*)d_in[5];
    const float* Wf = (const float*)d_in[6];
    const float* bf = (const float*)d_in[7];
    float* out = (float*)d_out;

    const int smem_bytes = 2 * ROWS * 256 * (int)sizeof(float);   // 32 KB
    cudaFuncSetAttribute(fused_kernel, cudaFuncAttributeMaxDynamicSharedMemorySize,
                         smem_bytes);

    poison_kernel<<<2048, 256>>>();
    fused_kernel<<<NCTA + NG, NTH, smem_bytes>>>(x, h0, W1, b1, W2, b2);
    final_kernel<<<1, 128>>>(Wf, bf, out);
    dummy_kernel<<<1, 32>>>();   // 4 launches/replay => ncu "-s 5" lands on fused_kernel
}

// round 17
// speedup vs baseline: 1.3984x; 1.3984x over previous
#include <cuda_runtime.h>
#include <cstdint>

#define TT 8192
#define DD 2048

typedef unsigned long long ull;

// ---------------- device scratch (no allocations allowed) ----------------
__device__ float g_pre[(size_t)TT * DD];        // 64 MB: pre = x @ W1^T + b1
__device__ float g_hs[(size_t)(TT + 1) * DD];   // 64 MB: h per step; sign bit = not-ready
#define TILES_M 64   // TT/128
#define TILES_N 16   // DD/128
__device__ int g_tile_cnt[TILES_M];             // per-m-tile completion counters

// ---------------- packed f32x2 helpers ----------------
__device__ __forceinline__ ull pk(float lo, float hi) {
    ull r;
    asm("mov.b64 %0, {%1, %2};" : "=l"(r) : "f"(lo), "f"(hi));
    return r;
}
__device__ __forceinline__ void upk(ull v, float& lo, float& hi) {
    asm("mov.b64 {%0, %1}, %2;" : "=f"(lo), "=f"(hi) : "l"(v));
}
__device__ __forceinline__ void fma2(ull& d, ull a, ull b) {
    asm("fma.rn.f32x2 %0, %1, %2, %0;" : "+l"(d) : "l"(a), "l"(b));
}

// ---------------- volatile ld/st (morally strong, guaranteed fresh+live) ----------
__device__ __forceinline__ uint4 ldvol_v4(const float* p) {
    uint4 v;
    asm volatile("ld.volatile.global.v4.u32 {%0,%1,%2,%3}, [%4];"
                 : "=r"(v.x), "=r"(v.y), "=r"(v.z), "=r"(v.w) : "l"(p));
    return v;
}
__device__ __forceinline__ void stvol_f32(float* p, float v) {
    asm volatile("st.volatile.global.f32 [%0], %1;" :: "l"(p), "f"(v));
}
__device__ __forceinline__ int ldvol_s32(const int* p) {
    int v;
    asm volatile("ld.volatile.global.s32 %0, [%1];" : "=r"(v) : "l"(p));
    return v;
}

// wait until pre m-tile is fully produced (checked once per 128 steps)
__device__ __forceinline__ void wait_tile(int m) {
    const int* p = g_tile_cnt + m;
    int v = ldvol_s32(p);
    while (v < TILES_N) {
        __nanosleep(160);
        v = ldvol_s32(p);
    }
    __threadfence();   // acquire: order subsequent pre reads after counter observation
}

// ---------------- poison kernel: not-ready sign bits + counter reset ----------
__global__ void poison_kernel() {
    if (blockIdx.x == 0 && threadIdx.x < TILES_M) g_tile_cnt[threadIdx.x] = 0;
    uint4 p = make_uint4(0xFFFFFFFFu, 0xFFFFFFFFu, 0xFFFFFFFFu, 0xFFFFFFFFu);
    size_t n = (size_t)(TT + 1) * DD / 4;
    uint4* dst = (uint4*)g_hs;
    for (size_t i = (size_t)blockIdx.x * blockDim.x + threadIdx.x; i < n;
         i += (size_t)gridDim.x * blockDim.x)
        dst[i] = p;
}

// ---------------- fused persistent kernel: scan CTAs + gemm CTAs ----------------
#define NCTA 128     // scan CTAs
#define NG   20      // gemm CTAs (remaining SMs; 148 total = all wave-1 resident)
#define NTH  512
#define ROWS 16      // DD / NCTA rows per scan CTA; warp w owns row blk*16+w
#define LDP 132      // padded gemm smem row

// ---- gemm part: 512 threads, persistent over tiles in m-major order ----
__device__ void gemm_part(float* smem, const float* __restrict__ A,
                          const float* __restrict__ B,
                          const float* __restrict__ bias, int g)
{
    float* As = smem;              // [16][LDP]
    float* Bs = smem + 16 * LDP;   // [16][LDP]
    const int tid = threadIdx.x;
    const int tx = tid & 31;       // 32 col-threads (4 cols each)
    const int ty = tid >> 5;       // 16 row-threads (8 rows each)
    const int lr = tid >> 2;       // load row 0..127
    const int lc = (tid & 3) * 4;  // load col group

    for (int idx = g; idx < TILES_M * TILES_N; idx += NG) {
        const int m0 = (idx >> 4) * 128;
        const int n0 = (idx & 15) * 128;

        ull acc[8][2];
#pragma unroll
        for (int r = 0; r < 8; r++) { acc[r][0] = 0ull; acc[r][1] = 0ull; }

        for (int k0 = 0; k0 < DD; k0 += 16) {
            float4 va = *(const float4*)(A + (size_t)(m0 + lr) * DD + k0 + lc);
            As[(lc + 0) * LDP + lr] = va.x; As[(lc + 1) * LDP + lr] = va.y;
            As[(lc + 2) * LDP + lr] = va.z; As[(lc + 3) * LDP + lr] = va.w;
            float4 vb = *(const float4*)(B + (size_t)(n0 + lr) * DD + k0 + lc);
            Bs[(lc + 0) * LDP + lr] = vb.x; Bs[(lc + 1) * LDP + lr] = vb.y;
            Bs[(lc + 2) * LDP + lr] = vb.z; Bs[(lc + 3) * LDP + lr] = vb.w;
            __syncthreads();

#pragma unroll
            for (int k = 0; k < 16; k++) {
                float4 a0 = *(const float4*)&As[k * LDP + ty * 8];
                float4 a1 = *(const float4*)&As[k * LDP + ty * 8 + 4];
                ulonglong2 bq = *(const ulonglong2*)&Bs[k * LDP + tx * 4];
                float ar[8] = {a0.x, a0.y, a0.z, a0.w, a1.x, a1.y, a1.z, a1.w};
#pragma unroll
                for (int r = 0; r < 8; r++) {
                    ull ad = pk(ar[r], ar[r]);
                    fma2(acc[r][0], ad, bq.x);
                    fma2(acc[r][1], ad, bq.y);
                }
            }
            __syncthreads();
        }

        // epilogue: bias + store
        float4 bb = *(const float4*)(bias + n0 + tx * 4);
#pragma unroll
        for (int r = 0; r < 8; r++) {
            float c0, c1, c2, c3;
            upk(acc[r][0], c0, c1);
            upk(acc[r][1], c2, c3);
            float4 o = make_float4(c0 + bb.x, c1 + bb.y, c2 + bb.z, c3 + bb.w);
            *(float4*)(g_pre + (size_t)(m0 + ty * 8 + r) * DD + n0 + tx * 4) = o;
        }

        __threadfence();      // release: pre stores visible before counter bump
        __syncthreads();
        if (tid == 0) atomicAdd(&g_tile_cnt[idx >> 4], 1);
        __syncthreads();
    }
}

// ---- scan step body (R14-proven form: scalar partials, 1 BAR, warp reduce) ----
struct StepCtx {
    ull w2r0[ROWS], w2r1[ROWS];
    int tid, lane, wid, myrow;
    float myb2;
};

__device__ __forceinline__ void step_body(
    const StepCtx& c, float* s_buf,
    float h0v, float h1v, float h2v, float h3v,
    float pre_cur, float* hstore)
{
    ull h01 = pk(h0v, h1v);
    ull h23 = pk(h2v, h3v);
#pragma unroll
    for (int j = 0; j < ROWS; j++) {
        ull acc = 0ull;
        fma2(acc, c.w2r0[j], h01);
        fma2(acc, c.w2r1[j], h23);
        float lo, hi;
        upk(acc, lo, hi);
        s_buf[j * NTH + c.tid] = lo + hi;
    }
    __syncthreads();

    const float* rowp = s_buf + c.wid * NTH;
    float s = 0.f;
#pragma unroll
    for (int i = 0; i < 4; i++) {
        float4 v = *(const float4*)(rowp + i * 128 + c.lane * 4);
        s += (v.x + v.y) + (v.z + v.w);
    }
    s += __shfl_xor_sync(0xffffffffu, s, 16);
    s += __shfl_xor_sync(0xffffffffu, s, 8);
    s += __shfl_xor_sync(0xffffffffu, s, 4);
    s += __shfl_xor_sync(0xffffffffu, s, 2);
    s += __shfl_xor_sync(0xffffffffu, s, 1);

    if (c.lane == 0) {
        float y = fmaxf(s + pre_cur + c.myb2, 0.f);
        y = __uint_as_float(__float_as_uint(y) & 0x7FFFFFFFu);  // sign bit = ready tag
        stvol_f32(hstore, y);
    }
    // no trailing barrier: double-buffered s_part + per-step BAR + dataflow poll
}

__global__ __launch_bounds__(NTH, 1) void fused_kernel(
    const float* __restrict__ x,
    const float* __restrict__ h0,
    const float* __restrict__ W1,
    const float* __restrict__ b1,
    const float* __restrict__ W2,
    const float* __restrict__ b2)
{
    extern __shared__ float smem[];   // scan: 2*ROWS*NTH floats (64KB); gemm: 17KB

    if (blockIdx.x >= NCTA) {         // ---- gemm CTAs ----
        gemm_part(smem, x, W1, b1, blockIdx.x - NCTA);
        return;
    }

    // ---- scan CTAs ----
    StepCtx c;
    c.tid  = threadIdx.x;
    c.lane = c.tid & 31;
    c.wid  = c.tid >> 5;
    const int blk = blockIdx.x;
    const int k0  = c.tid * 4;

#pragma unroll
    for (int j = 0; j < ROWS; j++) {
        float4 w = *(const float4*)(W2 + (size_t)(blk * ROWS + j) * DD + k0);
        c.w2r0[j] = pk(w.x, w.y);
        c.w2r1[j] = pk(w.z, w.w);
    }
    c.myrow = blk * ROWS + c.wid;
    c.myb2  = b2[c.myrow];

    wait_tile(0);                               // gate pre[0..127]
    float pre_next = __ldg(&g_pre[c.myrow]);

    // ---- step 0 (h0 is input; no poll, may be negative) ----
    {
        float4 hv = *(const float4*)(h0 + k0);
        float pre_cur = pre_next;
        pre_next = __ldg(&g_pre[(size_t)1 * DD + c.myrow]);
        step_body(c, smem, hv.x, hv.y, hv.z, hv.w, pre_cur,
                  &g_hs[(size_t)1 * DD + c.myrow]);
    }

    // ---- steps 1..TT-1 ----
    for (int t = 1; t < TT; t++) {
        const float* src = g_hs + (size_t)t * DD + k0;
        uint4 a = ldvol_v4(src);
        while (((a.x | a.y | a.z | a.w) & 0x80000000u) != 0u) {
            __nanosleep(96);            // slower poll: keep spin traffic under LTS cap
            a = ldvol_v4(src);
        }
        float pre_cur = pre_next;
        if (t + 1 < TT) {
            if (((t + 1) & 127) == 0) wait_tile((t + 1) >> 7);  // gate next m-tile
            pre_next = __ldg(&g_pre[(size_t)(t + 1) * DD + c.myrow]);
        }

        step_body(c, smem + (t & 1) * (ROWS * NTH),
                  __uint_as_float(a.x), __uint_as_float(a.y),
                  __uint_as_float(a.z), __uint_as_float(a.w),
                  pre_cur, &g_hs[(size_t)(t + 1) * DD + c.myrow]);
    }
}

// ---------------- final tiny matvec: out[j] = h . Wf[j] + bf[j] ----------------
__global__ void final_kernel(const float* __restrict__ Wf,
                             const float* __restrict__ bf,
                             float* __restrict__ out)
{
    const int wid = threadIdx.x >> 5;   // 4 warps, one per output row
    const int lane = threadIdx.x & 31;
    const float* h = g_hs + (size_t)TT * DD;
    const float* w = Wf + (size_t)wid * DD;
    float s = 0.f;
#pragma unroll
    for (int i = 0; i < 16; i++) {
        int k = i * 128 + lane * 4;
        float4 hv = *(const float4*)(h + k);
        float4 wv = *(const float4*)(w + k);
        s += hv.x * wv.x + hv.y * wv.y + hv.z * wv.z + hv.w * wv.w;
    }
    for (int off = 16; off; off >>= 1) s += __shfl_xor_sync(0xffffffffu, s, off);
    if (lane == 0) out[wid] = s + bf[wid];
}

// ---------------- launch ----------------
extern "C" void kernel_launch(void* const* d_in, const int* in_sizes, int n_in,
                              void* d_out, int out_size)
{
    const float* x  = (const float*)d_in[0];
    const float* h0 = (const float*)d_in[1];
    const float* W1 = (const float*)d_in[2];
    const float* b1 = (const float*)d_in[3];
    const float* W2 = (const float*)d_in[4];
    const float* b2 = (const float*)d_in[5];
    const float* Wf = (const float*)d_in[6];
    const float* bf = (const float*)d_in[7];
    float* out = (float*)d_out;

    const int smem_bytes = 2 * ROWS * NTH * (int)sizeof(float);   // 64 KB
    cudaFuncSetAttribute(fused_kernel, cudaFuncAttributeMaxDynamicSharedMemorySize,
                         smem_bytes);

    poison_kernel<<<2048, 256>>>();
    fused_kernel<<<NCTA + NG, NTH, smem_bytes>>>(x, h0, W1, b1, W2, b2);
    final_kernel<<<1, 128>>>(Wf, bf, out);
}